// round 7
// baseline (speedup 1.0000x reference)
#include <cuda_runtime.h>

#define T_BINS 151
#define TILE   64
#define PADW   132          // 128 + 4 floats pad: float4-aligned, bank-offset 4/row

// Global accumulators: [0..150] pos hist, [151..301] neg hist, [302] pos count.
// Zero-initialized at module load; the LAST block of every launch re-zeroes
// them after computing the loss, so every replay starts from zero (capture-safe,
// deterministic, no separate zero kernel).
__device__ float        g_hist[2 * T_BINS + 1];
__device__ unsigned int g_done;

__global__ __launch_bounds__(256) void hist_loss_kernel(
    const float* __restrict__ feats, const int* __restrict__ cls,
    float* __restrict__ out, int N, int NT, int nblocks)
{
    extern __shared__ float sm[];
    float* As   = sm;                         // TILE x PADW
    float* Bs   = As + TILE * PADW;           // TILE x PADW
    float* hist = Bs + TILE * PADW;           // 2 * T_BINS
    int*   clsA = (int*)(hist + 2 * T_BINS);  // TILE
    int*   clsB = clsA + TILE;                // TILE
    int*   sPos = clsB + TILE;                // 1
    __shared__ unsigned int s_ticket;

    const int tid = threadIdx.x;

    // Decode linear block id -> upper-triangular tile (bi, bj), bi <= bj.
    int k = blockIdx.x, bi = 0;
    while (k >= NT - bi) { k -= NT - bi; ++bi; }
    const int bj = bi + k;

    for (int i = tid; i < 2 * T_BINS; i += 256) hist[i] = 0.0f;
    if (tid == 0) *sPos = 0;
    if (tid < TILE) {
        int gi = bi * TILE + tid;
        clsA[tid] = (gi < N) ? cls[gi] : -1;
        int gj = bj * TILE + tid;
        clsB[tid] = (gj < N) ? cls[gj] : -2;
    }

    // Load both feature tiles (64 rows x 128 floats each) as float4, coalesced.
    const float4* f4 = (const float4*)feats;
    for (int idx = tid; idx < TILE * 32; idx += 256) {
        int r = idx >> 5, c = idx & 31;
        int gi = bi * TILE + r;
        float4 va = (gi < N) ? f4[gi * 32 + c] : make_float4(0.f, 0.f, 0.f, 0.f);
        *(float4*)(As + r * PADW + c * 4) = va;
        int gj = bj * TILE + r;
        float4 vb = (gj < N) ? f4[gj * 32 + c] : make_float4(0.f, 0.f, 0.f, 0.f);
        *(float4*)(Bs + r * PADW + c * 4) = vb;
    }
    __syncthreads();

    const int tr = tid >> 4;   // 0..15
    const int tc = tid & 15;   // 0..15

    // 4x4 register micro-tile: rows tr + 16u, cols tc + 16v.
    float acc[4][4];
#pragma unroll
    for (int u = 0; u < 4; ++u)
#pragma unroll
        for (int v = 0; v < 4; ++v) acc[u][v] = 0.0f;

    for (int kk = 0; kk < 128; kk += 4) {
        float4 a[4], b[4];
#pragma unroll
        for (int u = 0; u < 4; ++u)
            a[u] = *(const float4*)(As + (tr + 16 * u) * PADW + kk);
#pragma unroll
        for (int v = 0; v < 4; ++v)
            b[v] = *(const float4*)(Bs + (tc + 16 * v) * PADW + kk);
#pragma unroll
        for (int u = 0; u < 4; ++u)
#pragma unroll
            for (int v = 0; v < 4; ++v)
                acc[u][v] += a[u].x * b[v].x + a[u].y * b[v].y
                           + a[u].z * b[v].z + a[u].w * b[v].w;
    }

    // ---- Binning: bit-exact replication of the reference's fp32 semantics ----
    // Reference (all fp32, NO FMA contraction):
    //   delta = floor((s+1)/step)*step - 1
    //   indsb (bin q):    delta == -1 + q*step           -> ALWAYS true bitwise
    //   indsa (bin q+1):  delta == (-1+(q+1)*step) - step -> usually FALSE; wa dropped
    // q's divide stays __fdiv_rn (feeds bin index + edge equality). The weight
    // divides are continuous -> replaced by * inv_step (<=1ulp, ~1e-7 rel).
    const float step     = (float)(2.0 / 150.0);
    const float inv_step = __fdiv_rn(1.0f, step);
    int localPos = 0;
#pragma unroll
    for (int u = 0; u < 4; ++u) {
#pragma unroll
        for (int v = 0; v < 4; ++v) {
            int ri = tr + 16 * u, rj = tc + 16 * v;
            int gi = bi * TILE + ri, gj = bj * TILE + rj;
            if (gi < gj && gj < N) {
                float s     = acc[u][v];
                float q     = floorf(__fdiv_rn(__fadd_rn(s, 1.0f), step));
                float delta = __fsub_rn(__fmul_rn(q, step), 1.0f);  // == t_q bitwise
                int   j0    = (int)q;
                bool  eq    = (clsA[ri] == clsB[rj]);
                float* h    = eq ? hist : (hist + T_BINS);
                if (eq) ++localPos;
                // falling edge: wb into bin q (indsb always matches)
                if (j0 >= 0 && j0 < T_BINS) {
                    float wb = __fmul_rn(
                        __fadd_rn(__fadd_rn(-s, delta), step), inv_step);
                    atomicAdd(&h[j0], wb);
                }
                // rising edge: wa into bin q+1 ONLY on bitwise edge match
                int j1 = j0 + 1;
                if (j1 >= 0 && j1 < T_BINS) {
                    float t1 = __fadd_rn(-1.0f,
                               __fmul_rn(__fadd_rn(q, 1.0f), step));
                    if (delta == __fsub_rn(t1, step)) {
                        float wa = __fmul_rn(
                            __fadd_rn(__fsub_rn(s, t1), step), inv_step);
                        atomicAdd(&h[j1], wa);
                    }
                }
            }
        }
    }
    if (localPos) atomicAdd(sPos, localPos);
    __syncthreads();

    // Flush per-block shared histogram into the global accumulator (L2 atomics).
    for (int i = tid; i < 2 * T_BINS; i += 256) {
        float v = hist[i];
        if (v != 0.0f) atomicAdd(&g_hist[i], v);
    }
    if (tid == 0 && *sPos) atomicAdd(&g_hist[2 * T_BINS], (float)(*sPos));

    // ---- last-block-done finalize (no extra kernel launches) ----
    __threadfence();
    if (tid == 0) s_ticket = atomicInc(&g_done, 0xFFFFFFFFu);
    __syncthreads();
    if (s_ticket != (unsigned)(nblocks - 1)) return;

    // This is the last block; all other blocks' atomics are visible (fence+inc).
    __threadfence();

    float* hp  = hist;              // reuse shared memory
    float* hn  = hist + T_BINS;     // (hist region is 2*T_BINS floats)
    float* red = As;                // reuse tile A region for the reduce
    __shared__ float s_inv_pos, s_inv_neg;

    float vp = 0.f, vn = 0.f;
    if (tid < T_BINS) {
        vp = __ldcg(&g_hist[tid]);           // L2-coherent reads (atomics live in L2)
        vn = __ldcg(&g_hist[T_BINS + tid]);
    }
    if (tid == 0) {
        float cnt  = __ldcg(&g_hist[2 * T_BINS]);
        float Ptot = 0.5f * (float)N * (float)(N - 1);
        s_inv_pos = 1.0f / cnt;
        s_inv_neg = 1.0f / (Ptot - cnt);
    }
    __syncthreads();
    if (tid < T_BINS) {
        hp[tid] = vp * s_inv_pos;
        hn[tid] = vn * s_inv_neg;
    }
    __syncthreads();

    // inclusive scan of hp (Hillis-Steele, 8 steps)
    for (int off = 1; off < T_BINS; off <<= 1) {
        float v = (tid < T_BINS && tid >= off) ? hp[tid - off] : 0.f;
        __syncthreads();
        if (tid < T_BINS) hp[tid] += v;
        __syncthreads();
    }

    // dot(hn, cdf) via power-of-2 tree reduce over 256 slots
    red[tid] = (tid < T_BINS) ? hn[tid] * hp[tid] : 0.f;
    __syncthreads();
#pragma unroll
    for (int s = 128; s > 0; s >>= 1) {
        if (tid < s) red[tid] += red[tid + s];
        __syncthreads();
    }
    if (tid == 0) out[0] = red[0];

    // Reset globals for the next replay (invariant: zero at kernel entry).
    if (tid < 2 * T_BINS + 1) g_hist[tid] = 0.0f;
    else if (tid == 2 * T_BINS + 1) g_done = 0u;
    // (tid covers 0..302 and 303 within 256 threads? No: 2*T_BINS+1 = 303 > 256,
    //  so stride the reset properly below.)
    for (int i = tid + 256; i < 2 * T_BINS + 1; i += 256) g_hist[i] = 0.0f;
    if (tid == 0) g_done = 0u;
}

extern "C" void kernel_launch(void* const* d_in, const int* in_sizes, int n_in,
                              void* d_out, int out_size)
{
    const float* feats = (const float*)d_in[0];
    const int*   cls   = (const int*)d_in[1];
    int N  = in_sizes[1];                 // classes element count = number of rows
    int NT = (N + TILE - 1) / TILE;
    int nblocks = NT * (NT + 1) / 2;      // 136 for N=1024

    size_t smem = (size_t)(2 * TILE * PADW + 2 * T_BINS) * sizeof(float)
                + (size_t)(2 * TILE + 4) * sizeof(int);
    cudaFuncSetAttribute(hist_loss_kernel,
                         cudaFuncAttributeMaxDynamicSharedMemorySize, (int)smem);

    hist_loss_kernel<<<nblocks, 256, smem>>>(feats, cls, (float*)d_out,
                                             N, NT, nblocks);
}

// round 8
// speedup vs baseline: 1.1015x; 1.1015x over previous
#include <cuda_runtime.h>

#define T_BINS 151
#define TILE   64
#define PADW   132          // 128 + 4 floats pad: float4-aligned

// Global accumulators: [0..150] pos hist, [151..301] neg hist, [302] pos count.
// Zero at module load; the LAST block of every launch re-zeroes them after
// computing the loss -> every replay starts from zero (capture-safe).
__device__ float        g_hist[2 * T_BINS + 1];
__device__ unsigned int g_done;

__global__ __launch_bounds__(512) void hist_loss_kernel(
    const float* __restrict__ feats, const int* __restrict__ cls,
    float* __restrict__ out, int N, int NT, int nblocks)
{
    extern __shared__ float sm[];
    float* As   = sm;                         // TILE x PADW
    float* Bs   = As + TILE * PADW;           // TILE x PADW
    float* hist = Bs + TILE * PADW;           // 2 * T_BINS
    int*   clsA = (int*)(hist + 2 * T_BINS);  // TILE
    int*   clsB = clsA + TILE;                // TILE
    int*   sPos = clsB + TILE;                // 1

    // Per-bin constants (pure functions of the integer bin index j):
    //   t_lo[j]  = fl(fl(j*step) - 1)            == reference delta for q=j
    //   t_hi[j]  = fl(-1 + fl((j+1)*step))       == reference t_{q+1}
    //   allow[j] = (t_lo[j] == fl(t_hi[j]-step)) == reference indsa bitwise test
    __shared__ float t_lo[T_BINS];
    __shared__ float t_hi[T_BINS];
    __shared__ int   allow[T_BINS];
    __shared__ unsigned int s_ticket;

    const int tid = threadIdx.x;
    const float step     = (float)(2.0 / 150.0);
    const float inv_step = __fdiv_rn(1.0f, step);

    // Decode linear block id -> upper-triangular tile (bi, bj), bi <= bj.
    int k = blockIdx.x, bi = 0;
    while (k >= NT - bi) { k -= NT - bi; ++bi; }
    const int bj = bi + k;

    for (int i = tid; i < 2 * T_BINS; i += 512) hist[i] = 0.0f;
    if (tid == 0) *sPos = 0;
    if (tid < TILE) {
        int gi = bi * TILE + tid;
        clsA[tid] = (gi < N) ? cls[gi] : -1;
        int gj = bj * TILE + tid;
        clsB[tid] = (gj < N) ? cls[gj] : -2;
    }
    if (tid < T_BINS) {
        float qf = (float)tid;
        float d  = __fsub_rn(__fmul_rn(qf, step), 1.0f);
        float t1 = __fadd_rn(-1.0f, __fmul_rn(__fadd_rn(qf, 1.0f), step));
        t_lo[tid]  = d;
        t_hi[tid]  = t1;
        allow[tid] = (d == __fsub_rn(t1, step));
    }

    // Load both feature tiles (64 rows x 128 floats) as float4, coalesced.
    const float4* f4 = (const float4*)feats;
    for (int idx = tid; idx < TILE * 32; idx += 512) {
        int r = idx >> 5, c = idx & 31;
        int gi = bi * TILE + r;
        float4 va = (gi < N) ? f4[gi * 32 + c] : make_float4(0.f, 0.f, 0.f, 0.f);
        *(float4*)(As + r * PADW + c * 4) = va;
        int gj = bj * TILE + r;
        float4 vb = (gj < N) ? f4[gj * 32 + c] : make_float4(0.f, 0.f, 0.f, 0.f);
        *(float4*)(Bs + r * PADW + c * 4) = vb;
    }
    __syncthreads();

    // 2x4 micro-tile: rows {tr, tr+32}, cols {tc+16v}. 512 thr x 8 out = 64x64.
    const int tr = tid >> 4;   // 0..31
    const int tc = tid & 15;   // 0..15

    float acc[2][4];
#pragma unroll
    for (int u = 0; u < 2; ++u)
#pragma unroll
        for (int v = 0; v < 4; ++v) acc[u][v] = 0.0f;

    for (int kk = 0; kk < 128; kk += 4) {
        float4 a[2], b[4];
#pragma unroll
        for (int u = 0; u < 2; ++u)
            a[u] = *(const float4*)(As + (tr + 32 * u) * PADW + kk);
#pragma unroll
        for (int v = 0; v < 4; ++v)
            b[v] = *(const float4*)(Bs + (tc + 16 * v) * PADW + kk);
#pragma unroll
        for (int u = 0; u < 2; ++u)
#pragma unroll
            for (int v = 0; v < 4; ++v)
                acc[u][v] += a[u].x * b[v].x + a[u].y * b[v].y
                           + a[u].z * b[v].z + a[u].w * b[v].w;
    }

    // ---- Binning (reference fp32 semantics via per-bin tables) ----
    // wb always lands in bin q; wa lands in bin q+1 only when the reference's
    // bitwise edge equality holds (allow[q]). Weight divides -> * inv_step and
    // the q divide -> * inv_step: both perturb only ~ulp-boundary pairs whose
    // triangular weight is ~0 (argued <= 1e-6 rel; rel_err budget 1e-3).
    int localPos = 0;
#pragma unroll
    for (int u = 0; u < 2; ++u) {
#pragma unroll
        for (int v = 0; v < 4; ++v) {
            int ri = tr + 32 * u, rj = tc + 16 * v;
            int gi = bi * TILE + ri, gj = bj * TILE + rj;
            if (gi < gj && gj < N) {
                float s  = acc[u][v];
                float q  = floorf(__fmul_rn(__fadd_rn(s, 1.0f), inv_step));
                int   j0 = (int)q;
                bool  eq = (clsA[ri] == clsB[rj]);
                float* h = eq ? hist : (hist + T_BINS);
                if (eq) ++localPos;
                if (j0 >= 0 && j0 < T_BINS) {
                    float wb = __fmul_rn(
                        __fadd_rn(__fadd_rn(-s, t_lo[j0]), step), inv_step);
                    atomicAdd(&h[j0], wb);
                    if (j0 + 1 < T_BINS && allow[j0]) {
                        float wa = __fmul_rn(
                            __fadd_rn(__fsub_rn(s, t_hi[j0]), step), inv_step);
                        atomicAdd(&h[j0 + 1], wa);
                    }
                }
            }
        }
    }
    if (localPos) atomicAdd(sPos, localPos);
    __syncthreads();

    // Flush per-block shared histogram into the global accumulator (L2 atomics).
    for (int i = tid; i < 2 * T_BINS; i += 512) {
        float v = hist[i];
        if (v != 0.0f) atomicAdd(&g_hist[i], v);
    }
    if (tid == 0 && *sPos) atomicAdd(&g_hist[2 * T_BINS], (float)(*sPos));

    // ---- last-block-done finalize ----
    __threadfence();
    if (tid == 0) s_ticket = atomicInc(&g_done, 0xFFFFFFFFu);
    __syncthreads();
    if (s_ticket != (unsigned)(nblocks - 1)) return;
    __threadfence();

    float* hp  = hist;              // reuse shared memory
    float* hn  = hist + T_BINS;
    float* red = As;                // reuse tile A region (512 floats)
    __shared__ float s_inv_pos, s_inv_neg;

    float vp = 0.f, vn = 0.f;
    if (tid < T_BINS) {
        vp = __ldcg(&g_hist[tid]);
        vn = __ldcg(&g_hist[T_BINS + tid]);
    }
    if (tid == 0) {
        float cnt  = __ldcg(&g_hist[2 * T_BINS]);
        float Ptot = 0.5f * (float)N * (float)(N - 1);
        s_inv_pos = 1.0f / cnt;
        s_inv_neg = 1.0f / (Ptot - cnt);
    }
    __syncthreads();
    if (tid < T_BINS) {
        hp[tid] = vp * s_inv_pos;
        hn[tid] = vn * s_inv_neg;
    }
    __syncthreads();

    // inclusive scan of hp (Hillis-Steele, 8 steps)
    for (int off = 1; off < T_BINS; off <<= 1) {
        float v = (tid < T_BINS && tid >= off) ? hp[tid - off] : 0.f;
        __syncthreads();
        if (tid < T_BINS) hp[tid] += v;
        __syncthreads();
    }

    // dot(hn, cdf) via power-of-2 tree reduce over 512 slots
    red[tid] = (tid < T_BINS) ? hn[tid] * hp[tid] : 0.f;
    __syncthreads();
#pragma unroll
    for (int s = 256; s > 0; s >>= 1) {
        if (tid < s) red[tid] += red[tid + s];
        __syncthreads();
    }
    if (tid == 0) out[0] = red[0];

    // Reset globals for the next replay (invariant: zero at kernel entry).
    for (int i = tid; i < 2 * T_BINS + 1; i += 512) g_hist[i] = 0.0f;
    if (tid == 0) g_done = 0u;
}

extern "C" void kernel_launch(void* const* d_in, const int* in_sizes, int n_in,
                              void* d_out, int out_size)
{
    const float* feats = (const float*)d_in[0];
    const int*   cls   = (const int*)d_in[1];
    int N  = in_sizes[1];                 // classes element count = number of rows
    int NT = (N + TILE - 1) / TILE;
    int nblocks = NT * (NT + 1) / 2;      // 136 for N=1024

    size_t smem = (size_t)(2 * TILE * PADW + 2 * T_BINS) * sizeof(float)
                + (size_t)(2 * TILE + 4) * sizeof(int);
    cudaFuncSetAttribute(hist_loss_kernel,
                         cudaFuncAttributeMaxDynamicSharedMemorySize, (int)smem);

    hist_loss_kernel<<<nblocks, 512, smem>>>(feats, cls, (float*)d_out,
                                             N, NT, nblocks);
}